// round 3
// baseline (speedup 1.0000x reference)
#include <cuda_runtime.h>
#include <math.h>

#define N_TOK 32768
#define DIM 64
#define KCB 4096
#define TQ 64
#define TK 64
#define KSPLIT 4
#define KCHUNK (KCB / KSPLIT)
#define NTILES (KCHUNK / TK)

// -------- scratch (no allocations allowed) --------
__device__ float g_fn[N_TOK * DIM];
__device__ float g_cand_v[KSPLIT * N_TOK];
__device__ int   g_cand_i[KSPLIT * N_TOK];
__device__ int   g_idx[N_TOK];
__device__ int   g_usage[KCB];
__device__ float g_esum[KCB * DIM];
__device__ float g_newcs[KCB];
__device__ float g_scalars[4];

__device__ __forceinline__ float warp_sum(float v) {
#pragma unroll
    for (int o = 16; o > 0; o >>= 1) v += __shfl_xor_sync(0xffffffffu, v, o);
    return v;
}

// Threefry-2x32, 20 rounds (JAX PRNG)
__device__ __forceinline__ void threefry(unsigned k0, unsigned k1, unsigned x0, unsigned x1,
                                         unsigned &o0, unsigned &o1) {
    unsigned ks0 = k0, ks1 = k1, ks2 = k0 ^ k1 ^ 0x1BD11BDAu;
    const int R0[4] = {13, 15, 26, 6};
    const int R1[4] = {17, 29, 16, 24};
    x0 += ks0; x1 += ks1;
    unsigned ks[3] = {ks0, ks1, ks2};
#pragma unroll
    for (int g = 0; g < 5; ++g) {
        const int *R = (g & 1) ? R1 : R0;
#pragma unroll
        for (int r = 0; r < 4; ++r) {
            x0 += x1;
            x1 = (x1 << R[r]) | (x1 >> (32 - R[r]));
            x1 ^= x0;
        }
        x0 += ks[(g + 1) % 3];
        x1 += ks[(g + 2) % 3] + (unsigned)(g + 1);
    }
    o0 = x0; o1 = x1;
}

// -------- kernel 0: zero scratch accumulators --------
__global__ void zero_kernel() {
    int i = blockIdx.x * blockDim.x + threadIdx.x;
    if (i < KCB * DIM) g_esum[i] = 0.0f;
    if (i < KCB) g_usage[i] = 0;
}

// -------- kernel 1: flat_norm = z_e / clip(||z_e||, 1e-8), one warp per token --------
__global__ void norm_kernel(const float* __restrict__ z_e) {
    int gw = (blockIdx.x * blockDim.x + threadIdx.x) >> 5;
    int lane = threadIdx.x & 31;
    if (gw >= N_TOK) return;
    float2 v = ((const float2*)(z_e + (size_t)gw * DIM))[lane];
    float nrm = sqrtf(warp_sum(v.x * v.x + v.y * v.y));
    float c = fmaxf(nrm, 1e-8f);
    ((float2*)(g_fn + (size_t)gw * DIM))[lane] = make_float2(v.x / c, v.y / c);
}

// -------- kernel 2: fused fp32 GEMM + argmax over a K-chunk --------
// 16x16 threads, each computes a 4x4 fragment of dots; smem tiles stored [d][row].
__global__ __launch_bounds__(256) void argmax_kernel(const float* __restrict__ emb) {
    __shared__ float qs[DIM * TQ];
    __shared__ float es[DIM * TK];
    __shared__ float red_v[TQ][17];
    __shared__ int   red_i[TQ][17];

    int tid = threadIdx.x;
    int tx = tid & 15, ty = tid >> 4;
    int qblock = blockIdx.x * TQ;
    int kbase = blockIdx.y * KCHUNK;

    int lrow = tid >> 2;          // 0..63: row being staged
    int dg = (tid & 3) << 4;      // 0/16/32/48: d-group

    // stage query tile (transposed)
    {
        const float4* src = (const float4*)(g_fn + (size_t)(qblock + lrow) * DIM + dg);
#pragma unroll
        for (int j = 0; j < 4; ++j) {
            float4 v = src[j];
            int d0 = dg + j * 4;
            qs[(d0 + 0) * TQ + lrow] = v.x;
            qs[(d0 + 1) * TQ + lrow] = v.y;
            qs[(d0 + 2) * TQ + lrow] = v.z;
            qs[(d0 + 3) * TQ + lrow] = v.w;
        }
    }

    // preload embedding tile 0 into registers, store transposed
    float4 p[4];
    {
        const float4* src = (const float4*)(emb + (size_t)(kbase + lrow) * DIM + dg);
#pragma unroll
        for (int j = 0; j < 4; ++j) p[j] = src[j];
    }
#pragma unroll
    for (int j = 0; j < 4; ++j) {
        int d0 = dg + j * 4;
        es[(d0 + 0) * TK + lrow] = p[j].x;
        es[(d0 + 1) * TK + lrow] = p[j].y;
        es[(d0 + 2) * TK + lrow] = p[j].z;
        es[(d0 + 3) * TK + lrow] = p[j].w;
    }

    float bestv[4]; int besti[4];
#pragma unroll
    for (int i = 0; i < 4; ++i) { bestv[i] = -3.0e38f; besti[i] = 0; }

    __syncthreads();

    for (int kt = 0; kt < NTILES; ++kt) {
        bool has = (kt + 1 < NTILES);
        if (has) {
            const float4* src =
                (const float4*)(emb + (size_t)(kbase + (kt + 1) * TK + lrow) * DIM + dg);
#pragma unroll
            for (int j = 0; j < 4; ++j) p[j] = src[j];
        }

        float acc[4][4];
#pragma unroll
        for (int i = 0; i < 4; ++i)
#pragma unroll
            for (int j = 0; j < 4; ++j) acc[i][j] = 0.0f;

#pragma unroll
        for (int d = 0; d < DIM; ++d) {
            float4 qf = *(const float4*)&qs[d * TQ + (ty << 2)];
            float4 ef = *(const float4*)&es[d * TK + (tx << 2)];
            acc[0][0] += qf.x * ef.x; acc[0][1] += qf.x * ef.y;
            acc[0][2] += qf.x * ef.z; acc[0][3] += qf.x * ef.w;
            acc[1][0] += qf.y * ef.x; acc[1][1] += qf.y * ef.y;
            acc[1][2] += qf.y * ef.z; acc[1][3] += qf.y * ef.w;
            acc[2][0] += qf.z * ef.x; acc[2][1] += qf.z * ef.y;
            acc[2][2] += qf.z * ef.z; acc[2][3] += qf.z * ef.w;
            acc[3][0] += qf.w * ef.x; acc[3][1] += qf.w * ef.y;
            acc[3][2] += qf.w * ef.z; acc[3][3] += qf.w * ef.w;
        }

        int ebase = kbase + kt * TK + (tx << 2);
#pragma unroll
        for (int i = 0; i < 4; ++i)
#pragma unroll
            for (int j = 0; j < 4; ++j)
                if (acc[i][j] > bestv[i]) { bestv[i] = acc[i][j]; besti[i] = ebase + j; }

        if (has) {
            __syncthreads();
#pragma unroll
            for (int j = 0; j < 4; ++j) {
                int d0 = dg + j * 4;
                es[(d0 + 0) * TK + lrow] = p[j].x;
                es[(d0 + 1) * TK + lrow] = p[j].y;
                es[(d0 + 2) * TK + lrow] = p[j].z;
                es[(d0 + 3) * TK + lrow] = p[j].w;
            }
            __syncthreads();
        }
    }

    // cross-thread argmax reduction (tx ascending => lowest index wins on exact ties)
#pragma unroll
    for (int i = 0; i < 4; ++i) {
        red_v[(ty << 2) + i][tx] = bestv[i];
        red_i[(ty << 2) + i][tx] = besti[i];
    }
    __syncthreads();
    if (tid < TQ) {
        float bv = red_v[tid][0]; int bi = red_i[tid][0];
#pragma unroll
        for (int t = 1; t < 16; ++t) {
            float v = red_v[tid][t];
            if (v > bv) { bv = v; bi = red_i[tid][t]; }
        }
        g_cand_v[blockIdx.y * N_TOK + qblock + tid] = bv;
        g_cand_i[blockIdx.y * N_TOK + qblock + tid] = bi;
    }
}

// -------- kernel 3: merge K-split candidates (ascending split => lowest index on ties) --------
__global__ void merge_kernel(float* __restrict__ o_idx) {
    int n = blockIdx.x * blockDim.x + threadIdx.x;
    if (n >= N_TOK) return;
    float bv = g_cand_v[n]; int bi = g_cand_i[n];
#pragma unroll
    for (int s = 1; s < KSPLIT; ++s) {
        float v = g_cand_v[s * N_TOK + n];
        if (v > bv) { bv = v; bi = g_cand_i[s * N_TOK + n]; }
    }
    g_idx[n] = bi;
    o_idx[n] = (float)bi;
}

// -------- kernel 4: gather z_q / z_q_st, scatter usage + embed_sum --------
__global__ void gather_kernel(const float* __restrict__ z_e, const float* __restrict__ emb,
                              float* __restrict__ o_zqst, float* __restrict__ o_zq) {
    int gw = (blockIdx.x * blockDim.x + threadIdx.x) >> 5;
    int lane = threadIdx.x & 31;
    if (gw >= N_TOK) return;
    int idx = g_idx[gw];
    float2 v = ((const float2*)(emb + (size_t)idx * DIM))[lane];
    float2 ze = ((const float2*)(z_e + (size_t)gw * DIM))[lane];
    ((float2*)(o_zq + (size_t)gw * DIM))[lane] = v;
    ((float2*)(o_zqst + (size_t)gw * DIM))[lane] =
        make_float2(ze.x + (v.x - ze.x), ze.y + (v.y - ze.y));
    if (lane == 0) atomicAdd(&g_usage[idx], 1);
    float2 f = ((const float2*)(g_fn + (size_t)gw * DIM))[lane];
    atomicAdd(&g_esum[(size_t)idx * DIM + lane * 2 + 0], f.x);
    atomicAdd(&g_esum[(size_t)idx * DIM + lane * 2 + 1], f.y);
}

// -------- kernel 5: stats (perplexity, dead_ratio), new_cs, n = sum(new_cs) --------
__global__ void stats_kernel(const float* __restrict__ ema_cs,
                             float* __restrict__ o_stats, float* __restrict__ o_ncs) {
    __shared__ float sm[1024];
    int tid = threadIdx.x;
    float ent = 0.0f, dead = 0.0f, nsum = 0.0f;
    for (int k = tid; k < KCB; k += 1024) {
        float u = (float)g_usage[k];
        float pb = u * (1.0f / 32768.0f);    // usage.sum() == 32768 exactly
        if (u > 0.0f) ent += pb * logf(pb);
        else dead += 1.0f;
        float ncs = 0.99f * ema_cs[k] + 0.01f * u;
        g_newcs[k] = ncs;
        o_ncs[k] = ncs;
        nsum += ncs;
    }
    sm[tid] = ent; __syncthreads();
    for (int s = 512; s > 0; s >>= 1) { if (tid < s) sm[tid] += sm[tid + s]; __syncthreads(); }
    float tot_ent = sm[0]; __syncthreads();
    sm[tid] = dead; __syncthreads();
    for (int s = 512; s > 0; s >>= 1) { if (tid < s) sm[tid] += sm[tid + s]; __syncthreads(); }
    float tot_dead = sm[0]; __syncthreads();
    sm[tid] = nsum; __syncthreads();
    for (int s = 512; s > 0; s >>= 1) { if (tid < s) sm[tid] += sm[tid + s]; __syncthreads(); }
    if (tid == 0) {
        o_stats[0] = expf(-tot_ent);
        o_stats[1] = tot_dead * (1.0f / (float)KCB);
        g_scalars[0] = sm[0];
    }
}

// -------- kernel 6: EMA embedding update + normalize + dead-code reinit --------
__global__ void embed_kernel(const float* __restrict__ ema_emb,
                             float* __restrict__ o_nemb, float* __restrict__ o_nema) {
    int gw = (blockIdx.x * blockDim.x + threadIdx.x) >> 5;
    int lane = threadIdx.x & 31;
    if (gw >= KCB) return;
    int k = gw;
    float2 ee = ((const float2*)(ema_emb + (size_t)k * DIM))[lane];
    float2 es = ((const float2*)(g_esum + (size_t)k * DIM))[lane];
    float2 ne = make_float2(0.99f * ee.x + 0.01f * es.x, 0.99f * ee.y + 0.01f * es.y);
    ((float2*)(o_nema + (size_t)k * DIM))[lane] = ne;

    float n = g_scalars[0];
    float smoothed = (g_newcs[k] + 1e-5f) / (n + 0.04096f);   // K*EPS = 0.04096
    float s = fmaxf(smoothed, 1e-5f);
    float vx = ne.x / s, vy = ne.y / s;
    float nrm = sqrtf(warp_sum(vx * vx + vy * vy));
    float c = fmaxf(nrm, 1e-8f);
    float ox = vx / c, oy = vy / c;

    if (g_usage[k] == 0) {
        // rand_idx[k] via JAX threefry (partitionable layout):
        // k2 = split(key(1))[1] = threefry((0,1), (0,1)); bits = w0^w1 of threefry(k2,(0,k))
        unsigned a, b, o0, o1;
        threefry(0u, 1u, 0u, 1u, a, b);
        threefry(a, b, 0u, (unsigned)k, o0, o1);
        int r = (int)((o0 ^ o1) & 0x7FFFu);   // span 32768 (power of 2) => low 15 bits
        float2 f = ((const float2*)(g_fn + (size_t)r * DIM))[lane];
        float fn2 = warp_sum(f.x * f.x + f.y * f.y);
        float cc = fmaxf(sqrtf(fn2), 1e-8f);
        ox = f.x / cc; oy = f.y / cc;
    }
    ((float2*)(o_nemb + (size_t)k * DIM))[lane] = make_float2(ox, oy);
}

extern "C" void kernel_launch(void* const* d_in, const int* in_sizes, int n_in,
                              void* d_out, int out_size) {
    const float* z_e     = (const float*)d_in[0];   // (32,1024,64)
    const float* emb     = (const float*)d_in[1];   // (4096,64)
    const float* ema_cs  = (const float*)d_in[2];   // (4096,)
    const float* ema_emb = (const float*)d_in[3];   // (4096,64)

    float* out = (float*)d_out;
    // concatenated tuple layout (all float32):
    float* o_zqst  = out;                 // 2,097,152
    float* o_zq    = out + 2097152;       // 2,097,152
    float* o_idx   = out + 4194304;       //    32,768
    float* o_stats = out + 4227072;       //         2
    float* o_nemb  = out + 4227074;       //   262,144
    float* o_ncs   = out + 4489218;       //     4,096
    float* o_nema  = out + 4493314;       //   262,144

    zero_kernel<<<(KCB * DIM + 255) / 256, 256>>>();
    norm_kernel<<<(N_TOK * 32) / 256, 256>>>(z_e);
    dim3 ag(N_TOK / TQ, KSPLIT);
    argmax_kernel<<<ag, 256>>>(emb);
    merge_kernel<<<(N_TOK + 255) / 256, 256>>>(o_idx);
    gather_kernel<<<(N_TOK * 32) / 256, 256>>>(z_e, emb, o_zqst, o_zq);
    stats_kernel<<<1, 1024>>>(ema_cs, o_stats, o_ncs);
    embed_kernel<<<(KCB * 32) / 256, 256>>>(ema_emb, o_nemb, o_nema);
}

// round 5
// speedup vs baseline: 1.3911x; 1.3911x over previous
#include <cuda_runtime.h>
#include <math.h>

#define N_TOK 32768
#define DIM 64
#define KCB 4096
#define KSPLIT 4
#define KCHUNK (KCB / KSPLIT)

// ---- argmax tiling ----
#define TQ 128
#define TK 128
#define NTILES (KCHUNK / TK)      // 8
#define RSTRIDE 66                // padded row stride in floats (bank-conflict-free)
#define TILE_FLOATS (128 * RSTRIDE)

// -------- scratch (no allocations allowed) --------
__device__ float g_fn[N_TOK * DIM];
__device__ float g_cand_v[KSPLIT * N_TOK];
__device__ int   g_cand_i[KSPLIT * N_TOK];
__device__ int   g_idx[N_TOK];
__device__ int   g_usage[KCB];
__device__ float g_esum[KCB * DIM];
__device__ float g_newcs[KCB];
__device__ float g_scalars[4];

__device__ __forceinline__ float warp_sum(float v) {
#pragma unroll
    for (int o = 16; o > 0; o >>= 1) v += __shfl_xor_sync(0xffffffffu, v, o);
    return v;
}

// Threefry-2x32, 20 rounds (JAX PRNG)
__device__ __forceinline__ void threefry(unsigned k0, unsigned k1, unsigned x0, unsigned x1,
                                         unsigned &o0, unsigned &o1) {
    unsigned ks0 = k0, ks1 = k1, ks2 = k0 ^ k1 ^ 0x1BD11BDAu;
    const int R0[4] = {13, 15, 26, 6};
    const int R1[4] = {17, 29, 16, 24};
    x0 += ks0; x1 += ks1;
    unsigned ks[3] = {ks0, ks1, ks2};
#pragma unroll
    for (int g = 0; g < 5; ++g) {
        const int *R = (g & 1) ? R1 : R0;
#pragma unroll
        for (int r = 0; r < 4; ++r) {
            x0 += x1;
            x1 = (x1 << R[r]) | (x1 >> (32 - R[r]));
            x1 ^= x0;
        }
        x0 += ks[(g + 1) % 3];
        x1 += ks[(g + 2) % 3] + (unsigned)(g + 1);
    }
    o0 = x0; o1 = x1;
}

__device__ __forceinline__ unsigned smem_u32(const void* p) {
    unsigned r;
    asm("{ .reg .u64 t; cvta.to.shared.u64 t, %1; cvt.u32.u64 %0, t; }" : "=r"(r) : "l"(p));
    return r;
}

__device__ __forceinline__ void cp8(unsigned dst, const float* src) {
    asm volatile("cp.async.ca.shared.global [%0], [%1], 8;" :: "r"(dst), "l"(src));
}

// stage a 128-row x 64-float tile (row-major global) into padded smem (stride 66)
__device__ __forceinline__ void stage_tile(unsigned sbase_bytes, const float* __restrict__ g,
                                           int tid) {
#pragma unroll
    for (int r = 0; r < 16; ++r) {
        int c = r * 256 + tid;            // 0..4095 chunk id (8B chunks)
        int row = c >> 5, dp = c & 31;
        cp8(sbase_bytes + (unsigned)(row * RSTRIDE + dp * 2) * 4u, g + c * 2);
    }
}

// -------- kernel 0: zero scratch accumulators --------
__global__ void zero_kernel() {
    int i = blockIdx.x * blockDim.x + threadIdx.x;
    if (i < KCB * DIM) g_esum[i] = 0.0f;
    if (i < KCB) g_usage[i] = 0;
}

// -------- kernel 1: flat_norm = z_e / clip(||z_e||, 1e-8), one warp per token --------
__global__ void norm_kernel(const float* __restrict__ z_e) {
    int gw = (blockIdx.x * blockDim.x + threadIdx.x) >> 5;
    int lane = threadIdx.x & 31;
    if (gw >= N_TOK) return;
    float2 v = ((const float2*)(z_e + (size_t)gw * DIM))[lane];
    float nrm = sqrtf(warp_sum(v.x * v.x + v.y * v.y));
    float c = fmaxf(nrm, 1e-8f);
    ((float2*)(g_fn + (size_t)gw * DIM))[lane] = make_float2(v.x / c, v.y / c);
}

// -------- kernel 2: fused fp32 GEMM + argmax (f32x2 packed FMA, d-parity packing) --------
// 256 threads = 16x16 grid; thread (tx,ty) owns q rows {i*16+ty}, e rows {j*16+tx}, 8x8 frag.
// Accumulators are f32x2 packed over (d even, d odd); dot = lo + hi at tile end.
__global__ __launch_bounds__(256, 1) void argmax_kernel(const float* __restrict__ emb) {
    extern __shared__ float sm[];
    float* qs  = sm;
    float* es0 = sm + TILE_FLOATS;
    float* es1 = es0 + TILE_FLOATS;

    int tid = threadIdx.x;
    int tx = tid & 15, ty = tid >> 4;
    int qblock = blockIdx.x * TQ;
    int kbase = blockIdx.y * KCHUNK;

    unsigned sb  = smem_u32(sm);
    unsigned e0b = sb + TILE_FLOATS * 4u;
    unsigned e1b = e0b + TILE_FLOATS * 4u;

    stage_tile(sb, g_fn + (size_t)qblock * DIM, tid);
    stage_tile(e0b, emb + (size_t)kbase * DIM, tid);
    asm volatile("cp.async.commit_group;" ::: "memory");
    asm volatile("cp.async.wait_group 0;" ::: "memory");
    __syncthreads();

    float bestv[8]; int besti[8];
#pragma unroll
    for (int i = 0; i < 8; ++i) { bestv[i] = -3.0e38f; besti[i] = 0; }

    const float* qp0 = qs + ty * RSTRIDE;

    for (int kt = 0; kt < NTILES; ++kt) {
        const float* eb = (kt & 1) ? es1 : es0;
        if (kt + 1 < NTILES) {
            unsigned nb = (kt & 1) ? e0b : e1b;
            stage_tile(nb, emb + (size_t)(kbase + (kt + 1) * TK) * DIM, tid);
            asm volatile("cp.async.commit_group;" ::: "memory");
        }
        const float* ep0 = eb + tx * RSTRIDE;

        unsigned long long acc[8][8];
#pragma unroll
        for (int i = 0; i < 8; ++i)
#pragma unroll
            for (int j = 0; j < 8; ++j) acc[i][j] = 0ull;

#pragma unroll 8
        for (int dp = 0; dp < 32; ++dp) {
            unsigned long long qv[8], ev[4];
#pragma unroll
            for (int i = 0; i < 8; ++i)
                qv[i] = *(const unsigned long long*)(qp0 + i * 16 * RSTRIDE + dp * 2);
            // first half of e-fragment
#pragma unroll
            for (int j = 0; j < 4; ++j)
                ev[j] = *(const unsigned long long*)(ep0 + j * 16 * RSTRIDE + dp * 2);
#pragma unroll
            for (int i = 0; i < 8; ++i)
#pragma unroll
                for (int j = 0; j < 4; ++j)
                    asm("fma.rn.f32x2 %0, %1, %2, %0;"
                        : "+l"(acc[i][j]) : "l"(qv[i]), "l"(ev[j]));
            // second half of e-fragment (reuses ev regs -> lower peak pressure)
#pragma unroll
            for (int j = 0; j < 4; ++j)
                ev[j] = *(const unsigned long long*)(ep0 + (j + 4) * 16 * RSTRIDE + dp * 2);
#pragma unroll
            for (int i = 0; i < 8; ++i)
#pragma unroll
                for (int j = 0; j < 4; ++j)
                    asm("fma.rn.f32x2 %0, %1, %2, %0;"
                        : "+l"(acc[i][j + 4]) : "l"(qv[i]), "l"(ev[j]));
        }

        int kb = kbase + kt * TK + tx;
#pragma unroll
        for (int i = 0; i < 8; ++i)
#pragma unroll
            for (int j = 0; j < 8; ++j) {
                float2 a = *(float2*)&acc[i][j];
                float d = a.x + a.y;
                if (d > bestv[i]) { bestv[i] = d; besti[i] = kb + j * 16; }
            }

        if (kt + 1 < NTILES)
            asm volatile("cp.async.wait_group 0;" ::: "memory");
        __syncthreads();
    }

    // cross-thread argmax reduction (reuse qs region; all compute done per barrier above)
    float* red_v = qs;                       // [128][17]
    int*   red_i = (int*)(qs + TQ * 17);
#pragma unroll
    for (int i = 0; i < 8; ++i) {
        int r = i * 16 + ty;
        red_v[r * 17 + tx] = bestv[i];
        red_i[r * 17 + tx] = besti[i];
    }
    __syncthreads();
    if (tid < TQ) {
        float bv = red_v[tid * 17]; int bi = red_i[tid * 17];
#pragma unroll
        for (int t = 1; t < 16; ++t) {
            float v = red_v[tid * 17 + t];
            if (v > bv) { bv = v; bi = red_i[tid * 17 + t]; }
        }
        g_cand_v[blockIdx.y * N_TOK + qblock + tid] = bv;
        g_cand_i[blockIdx.y * N_TOK + qblock + tid] = bi;
    }
}

// -------- kernel 3: merge K-split candidates (ascending split => lowest index on ties) --------
__global__ void merge_kernel(float* __restrict__ o_idx) {
    int n = blockIdx.x * blockDim.x + threadIdx.x;
    if (n >= N_TOK) return;
    float bv = g_cand_v[n]; int bi = g_cand_i[n];
#pragma unroll
    for (int s = 1; s < KSPLIT; ++s) {
        float v = g_cand_v[s * N_TOK + n];
        if (v > bv) { bv = v; bi = g_cand_i[s * N_TOK + n]; }
    }
    g_idx[n] = bi;
    o_idx[n] = (float)bi;
}

// -------- kernel 4: gather z_q / z_q_st, scatter usage + embed_sum --------
__global__ void gather_kernel(const float* __restrict__ z_e, const float* __restrict__ emb,
                              float* __restrict__ o_zqst, float* __restrict__ o_zq) {
    int gw = (blockIdx.x * blockDim.x + threadIdx.x) >> 5;
    int lane = threadIdx.x & 31;
    if (gw >= N_TOK) return;
    int idx = g_idx[gw];
    float2 v = ((const float2*)(emb + (size_t)idx * DIM))[lane];
    float2 ze = ((const float2*)(z_e + (size_t)gw * DIM))[lane];
    ((float2*)(o_zq + (size_t)gw * DIM))[lane] = v;
    ((float2*)(o_zqst + (size_t)gw * DIM))[lane] =
        make_float2(ze.x + (v.x - ze.x), ze.y + (v.y - ze.y));
    if (lane == 0) atomicAdd(&g_usage[idx], 1);
    float2 f = ((const float2*)(g_fn + (size_t)gw * DIM))[lane];
    atomicAdd(&g_esum[(size_t)idx * DIM + lane * 2 + 0], f.x);
    atomicAdd(&g_esum[(size_t)idx * DIM + lane * 2 + 1], f.y);
}

// -------- kernel 5: stats (perplexity, dead_ratio), new_cs, n = sum(new_cs) --------
__global__ void stats_kernel(const float* __restrict__ ema_cs,
                             float* __restrict__ o_stats, float* __restrict__ o_ncs) {
    __shared__ float sm[1024];
    int tid = threadIdx.x;
    float ent = 0.0f, dead = 0.0f, nsum = 0.0f;
    for (int k = tid; k < KCB; k += 1024) {
        float u = (float)g_usage[k];
        float pb = u * (1.0f / 32768.0f);    // usage.sum() == 32768 exactly
        if (u > 0.0f) ent += pb * logf(pb);
        else dead += 1.0f;
        float ncs = 0.99f * ema_cs[k] + 0.01f * u;
        g_newcs[k] = ncs;
        o_ncs[k] = ncs;
        nsum += ncs;
    }
    sm[tid] = ent; __syncthreads();
    for (int s = 512; s > 0; s >>= 1) { if (tid < s) sm[tid] += sm[tid + s]; __syncthreads(); }
    float tot_ent = sm[0]; __syncthreads();
    sm[tid] = dead; __syncthreads();
    for (int s = 512; s > 0; s >>= 1) { if (tid < s) sm[tid] += sm[tid + s]; __syncthreads(); }
    float tot_dead = sm[0]; __syncthreads();
    sm[tid] = nsum; __syncthreads();
    for (int s = 512; s > 0; s >>= 1) { if (tid < s) sm[tid] += sm[tid + s]; __syncthreads(); }
    if (tid == 0) {
        o_stats[0] = expf(-tot_ent);
        o_stats[1] = tot_dead * (1.0f / (float)KCB);
        g_scalars[0] = sm[0];
    }
}

// -------- kernel 6: EMA embedding update + normalize + dead-code reinit --------
__global__ void embed_kernel(const float* __restrict__ ema_emb,
                             float* __restrict__ o_nemb, float* __restrict__ o_nema) {
    int gw = (blockIdx.x * blockDim.x + threadIdx.x) >> 5;
    int lane = threadIdx.x & 31;
    if (gw >= KCB) return;
    int k = gw;
    float2 ee = ((const float2*)(ema_emb + (size_t)k * DIM))[lane];
    float2 es = ((const float2*)(g_esum + (size_t)k * DIM))[lane];
    float2 ne = make_float2(0.99f * ee.x + 0.01f * es.x, 0.99f * ee.y + 0.01f * es.y);
    ((float2*)(o_nema + (size_t)k * DIM))[lane] = ne;

    float n = g_scalars[0];
    float smoothed = (g_newcs[k] + 1e-5f) / (n + 0.04096f);   // K*EPS = 0.04096
    float s = fmaxf(smoothed, 1e-5f);
    float vx = ne.x / s, vy = ne.y / s;
    float nrm = sqrtf(warp_sum(vx * vx + vy * vy));
    float c = fmaxf(nrm, 1e-8f);
    float ox = vx / c, oy = vy / c;

    if (g_usage[k] == 0) {
        // rand_idx[k] via JAX threefry (partitionable layout):
        // k2 = split(key(1))[1] = threefry((0,1), (0,1)); bits = w0^w1 of threefry(k2,(0,k))
        unsigned a, b, o0, o1;
        threefry(0u, 1u, 0u, 1u, a, b);
        threefry(a, b, 0u, (unsigned)k, o0, o1);
        int r = (int)((o0 ^ o1) & 0x7FFFu);   // span 32768 (power of 2) => low 15 bits
        float2 f = ((const float2*)(g_fn + (size_t)r * DIM))[lane];
        float fn2 = warp_sum(f.x * f.x + f.y * f.y);
        float cc = fmaxf(sqrtf(fn2), 1e-8f);
        ox = f.x / cc; oy = f.y / cc;
    }
    ((float2*)(o_nemb + (size_t)k * DIM))[lane] = make_float2(ox, oy);
}

extern "C" void kernel_launch(void* const* d_in, const int* in_sizes, int n_in,
                              void* d_out, int out_size) {
    const float* z_e     = (const float*)d_in[0];   // (32,1024,64)
    const float* emb     = (const float*)d_in[1];   // (4096,64)
    const float* ema_cs  = (const float*)d_in[2];   // (4096,)
    const float* ema_emb = (const float*)d_in[3];   // (4096,64)

    float* out = (float*)d_out;
    // concatenated tuple layout (all float32):
    float* o_zqst  = out;                 // 2,097,152
    float* o_zq    = out + 2097152;       // 2,097,152
    float* o_idx   = out + 4194304;       //    32,768
    float* o_stats = out + 4227072;       //         2
    float* o_nemb  = out + 4227074;       //   262,144
    float* o_ncs   = out + 4489218;       //     4,096
    float* o_nema  = out + 4493314;       //   262,144

    cudaFuncSetAttribute(argmax_kernel, cudaFuncAttributeMaxDynamicSharedMemorySize,
                         3 * TILE_FLOATS * 4);

    zero_kernel<<<(KCB * DIM + 255) / 256, 256>>>();
    norm_kernel<<<(N_TOK * 32) / 256, 256>>>(z_e);
    dim3 ag(N_TOK / TQ, KSPLIT);
    argmax_kernel<<<ag, 256, 3 * TILE_FLOATS * 4>>>(emb);
    merge_kernel<<<(N_TOK + 255) / 256, 256>>>(o_idx);
    gather_kernel<<<(N_TOK * 32) / 256, 256>>>(z_e, emb, o_zqst, o_zq);
    stats_kernel<<<1, 1024>>>(ema_cs, o_stats, o_ncs);
    embed_kernel<<<(KCB * 32) / 256, 256>>>(ema_emb, o_nemb, o_nema);
}